// round 6
// baseline (speedup 1.0000x reference)
#include <cuda_runtime.h>
#include <cuda_bf16.h>
#include <cstdint>
#include <math.h>

// ---------------------------------------------------------------------------
// Problem constants
// ---------------------------------------------------------------------------
#define N_FEAT 131072
#define D      128
#define K      1024
#define TM     128            // rows per CTA
#define TN     128            // centers per B-tile
#define NTILE  (K / TN)       // 8
#define NBLK   (N_FEAT / TM)  // 1024

#define RAW_BYTES (TM * D * 4)     // 65536 raw fp32 rows
#define A_BYTES   (TM * D * 2)     // 32768 bf16-hi tile (256B rows)
#define B_BYTES   (TN * D * 2)     // 32768 per B tile

// SMEM map (dynamic)
#define SM_CTRL 0                   // mbarriers
#define SM_RINV 128                 // 128 floats
#define SM_RAW  1024
#define SM_AH   (SM_RAW + RAW_BYTES)
#define SM_B0   (SM_AH + A_BYTES)
#define SM_B1   (SM_B0 + B_BYTES)
#define SMEM_TOTAL (SM_B1 + B_BYTES)   // 164864
// epilogue scratch overlays the (dead) B0 region
#define SM_REDS SM_B0
#define SM_REDI (SM_B0 + 8192)
#define SM_LSUM (SM_B0 + 16384)

#define MB_RAW 0
#define MB_B0  8
#define MB_B1  16

// ---------------------------------------------------------------------------
// Device scratch
// ---------------------------------------------------------------------------
__device__ __align__(1024) unsigned char g_B[NTILE * B_BYTES];  // 256 KB
__device__ float g_cnormsq[K];
__device__ float g_partial[NBLK];
__device__ unsigned int g_ctr;   // zero-init; reset by last block each run

// ---------------------------------------------------------------------------
// PTX helpers
// ---------------------------------------------------------------------------
__device__ __forceinline__ uint32_t smem_u32(const void* p) {
    uint32_t a;
    asm("{ .reg .u64 t; cvta.to.shared.u64 t, %1; cvt.u32.u64 %0, t; }" : "=r"(a) : "l"(p));
    return a;
}
#define MBAR_INIT(a, c) \
    asm volatile("mbarrier.init.shared.b64 [%0], %1;" :: "r"((uint32_t)(a)), "r"((uint32_t)(c)) : "memory")
#define MBAR_EXPECT_TX(a, b) \
    asm volatile("mbarrier.arrive.expect_tx.shared.b64 _, [%0], %1;" :: "r"((uint32_t)(a)), "r"((uint32_t)(b)) : "memory")
#define MBAR_WAIT(a, ph) do { \
    uint32_t _m = (uint32_t)(a), _p = (uint32_t)(ph), _d; \
    asm volatile("{ .reg .pred p; mbarrier.try_wait.parity.acquire.cta.shared::cta.b64 p, [%1], %2; selp.b32 %0,1,0,p; }" \
        : "=r"(_d) : "r"(_m), "r"(_p) : "memory"); \
    if (!_d) { \
        asm volatile("{ .reg .pred P1; WL%=: mbarrier.try_wait.parity.acquire.cta.shared::cta.b64 P1, [%0], %1, 0x989680; @P1 bra.uni WD%=; bra.uni WL%=; WD%=: }" \
            :: "r"(_m), "r"(_p) : "memory"); \
    } \
} while (0)

__device__ __forceinline__ void bulk_g2s(uint32_t dst, const void* src,
                                         uint32_t bytes, uint32_t mbar) {
    asm volatile(
        "cp.async.bulk.shared::cta.global.mbarrier::complete_tx::bytes [%0], [%1], %2, [%3];"
        :: "r"(dst), "l"(src), "r"(bytes), "r"(mbar) : "memory");
}
#define LDSM_X4(r, a) \
    asm volatile("ldmatrix.sync.aligned.m8n8.x4.shared.b16 {%0,%1,%2,%3}, [%4];" \
        : "=r"((r)[0]), "=r"((r)[1]), "=r"((r)[2]), "=r"((r)[3]) : "r"(a))
#define MMA_BF16(c, a, b0_, b1_) \
    asm volatile("mma.sync.aligned.m16n8k16.row.col.f32.bf16.bf16.f32 " \
        "{%0,%1,%2,%3}, {%4,%5,%6,%7}, {%8,%9}, {%0,%1,%2,%3};" \
        : "+f"((c)[0]), "+f"((c)[1]), "+f"((c)[2]), "+f"((c)[3]) \
        : "r"((a)[0]), "r"((a)[1]), "r"((a)[2]), "r"((a)[3]), "r"(b0_), "r"(b1_))

__device__ __forceinline__ unsigned short bf16_bits(__nv_bfloat16 h) {
    return *reinterpret_cast<unsigned short*>(&h);
}
__device__ __forceinline__ unsigned int pack_bf2(float a, float b) {
    return (unsigned)bf16_bits(__float2bfloat16(a)) |
           ((unsigned)bf16_bits(__float2bfloat16(b)) << 16);
}

// ---------------------------------------------------------------------------
// Prep: centers -> normalize; bf16-hi into g_B [tile][128n][128k], 256B rows,
// chunk swizzle: chunk = (d>>3) ^ (n&7)
// ---------------------------------------------------------------------------
__global__ void prep_centers(const float* __restrict__ centers) {
    int k = blockIdx.x;
    int d = threadIdx.x;  // 128
    float v = centers[k * D + d];
    float s = v * v;
    #pragma unroll
    for (int o = 16; o; o >>= 1) s += __shfl_down_sync(0xffffffffu, s, o);
    __shared__ float ws[4];
    if ((d & 31) == 0) ws[d >> 5] = s;
    __syncthreads();
    float tot  = ws[0] + ws[1] + ws[2] + ws[3];
    float norm = sqrtf(tot);
    float x = v / fmaxf(norm, 1e-12f);
    unsigned char* tile = g_B + (size_t)(k >> 7) * B_BYTES;
    int nn = k & 127;
    uint32_t off = (uint32_t)(nn * 256 + ((((d >> 3) ^ (nn & 7)) & 15) << 4) + (d & 7) * 2);
    *(unsigned short*)(tile + off) = bf16_bits(__float2bfloat16(x));
    if (d == 0) g_cnormsq[k] = tot;
}

// ---------------------------------------------------------------------------
// Main: raw-A load + in-kernel normalize/convert, mma.sync bf16 GEMM (K=128),
// fused argmax, EXACT fp32 loss epilogue, last-block final reduction.
// 8 warps: warp_m = wid>>2 (2), warp_n = wid&3 (4); warp tile 64x32
// ---------------------------------------------------------------------------
__global__ __launch_bounds__(256, 1)
void gemm_argmax_mma(const float* __restrict__ features,
                     const float* __restrict__ centers,
                     float* __restrict__ out) {
    extern __shared__ __align__(1024) unsigned char smem[];
    uint32_t sb = smem_u32(smem);
    const int tid = threadIdx.x;
    const int wid = tid >> 5, l = tid & 31;
    const int warp_m = wid >> 2, warp_n = wid & 3;

    if (tid == 0) {
        MBAR_INIT(sb + SM_CTRL + MB_RAW, 1);
        MBAR_INIT(sb + SM_CTRL + MB_B0, 1);
        MBAR_INIT(sb + SM_CTRL + MB_B1, 1);
    }
    __syncthreads();
    if (tid == 0) {
        MBAR_EXPECT_TX(sb + SM_CTRL + MB_RAW, RAW_BYTES);
        bulk_g2s(sb + SM_RAW, features + (size_t)blockIdx.x * TM * D,
                 RAW_BYTES, sb + SM_CTRL + MB_RAW);
        MBAR_EXPECT_TX(sb + SM_CTRL + MB_B0, B_BYTES);
        bulk_g2s(sb + SM_B0, g_B, B_BYTES, sb + SM_CTRL + MB_B0);
    }

    // ---- in-kernel A prep: norms + bf16-hi conversion ----
    MBAR_WAIT(sb + SM_CTRL + MB_RAW, 0);
    if (tid < TM) {
        const float4* raw4 = (const float4*)(smem + SM_RAW + tid * 512);
        float s = 0.0f;
        #pragma unroll
        for (int j = 0; j < 32; j++) {
            float4 v = raw4[(j + tid) & 31];   // rotated: conflict-free
            s += v.x * v.x + v.y * v.y + v.z * v.z + v.w * v.w;
        }
        float rinv = 1.0f / fmaxf(sqrtf(s), 1e-12f);
        ((float*)(smem + SM_RINV))[tid] = rinv;
        unsigned char* arow = smem + SM_AH + tid * 256;
        #pragma unroll
        for (int j = 0; j < 16; j++) {
            int fc = (j + tid) & 15;           // final (swizzled) chunk
            int c  = fc ^ (tid & 7);           // logical chunk -> dims c*8..c*8+7
            float4 v0 = raw4[c * 2];
            float4 v1 = raw4[c * 2 + 1];
            uint4 o;
            o.x = pack_bf2(v0.x * rinv, v0.y * rinv);
            o.y = pack_bf2(v0.z * rinv, v0.w * rinv);
            o.z = pack_bf2(v1.x * rinv, v1.y * rinv);
            o.w = pack_bf2(v1.z * rinv, v1.w * rinv);
            *(uint4*)(arow + (fc << 4)) = o;
        }
    }
    __syncthreads();

    // ldmatrix lane geometry (validated round 5; non-trans B)
    const int a_row_in = (l & 7) + ((l >> 3) & 1) * 8;
    const int a_cb     = (l >> 4);
    const int b_row_in = (l & 7) + ((l >> 4) & 1) * 8;
    const int b_cb     = (l >> 3) & 1;

    float best[8];
    int   bidx[8];
    #pragma unroll
    for (int i = 0; i < 8; i++) { best[i] = -1e30f; bidx[i] = 0; }

    for (int t = 0; t < NTILE; t++) {
        const uint32_t bbuf = (t & 1) ? (sb + SM_B1) : (sb + SM_B0);
        MBAR_WAIT(sb + SM_CTRL + ((t & 1) ? MB_B1 : MB_B0), (t >> 1) & 1);
        if (tid == 0 && t + 1 < NTILE) {
            uint32_t mb = sb + SM_CTRL + (((t + 1) & 1) ? MB_B1 : MB_B0);
            MBAR_EXPECT_TX(mb, B_BYTES);
            bulk_g2s(((t + 1) & 1) ? (sb + SM_B1) : (sb + SM_B0),
                     g_B + (size_t)(t + 1) * B_BYTES, B_BYTES, mb);
        }

        float acc[4][4][4];
        #pragma unroll
        for (int mi = 0; mi < 4; mi++)
            #pragma unroll
            for (int ni = 0; ni < 4; ni++)
                #pragma unroll
                for (int e = 0; e < 4; e++) acc[mi][ni][e] = 0.0f;

        #pragma unroll
        for (int kk = 0; kk < 8; kk++) {
            uint32_t af[4][4];
            #pragma unroll
            for (int mi = 0; mi < 4; mi++) {
                int row = warp_m * 64 + mi * 16 + a_row_in;
                uint32_t addr = sb + SM_AH + row * 256 +
                                (((kk * 2 + a_cb) ^ (row & 7)) << 4);
                LDSM_X4(af[mi], addr);
            }
            uint32_t bfm[2][4];
            #pragma unroll
            for (int bp = 0; bp < 2; bp++) {
                int nrow = warp_n * 32 + bp * 16 + b_row_in;
                uint32_t addr = bbuf + nrow * 256 +
                                (((kk * 2 + b_cb) ^ (nrow & 7)) << 4);
                LDSM_X4(bfm[bp], addr);
            }
            #pragma unroll
            for (int mi = 0; mi < 4; mi++)
                #pragma unroll
                for (int ni = 0; ni < 4; ni++)
                    MMA_BF16(acc[mi][ni], af[mi],
                             bfm[ni >> 1][(ni & 1) * 2], bfm[ni >> 1][(ni & 1) * 2 + 1]);
        }

        #pragma unroll
        for (int mi = 0; mi < 4; mi++) {
            #pragma unroll
            for (int ni = 0; ni < 4; ni++) {
                int k0 = t * TN + warp_n * 32 + ni * 8 + (l & 3) * 2;
                float c0 = acc[mi][ni][0], c1 = acc[mi][ni][1];
                float c2 = acc[mi][ni][2], c3 = acc[mi][ni][3];
                int i0 = mi * 2, i1 = mi * 2 + 1;
                if (c0 > best[i0]) { best[i0] = c0; bidx[i0] = k0; }
                if (c1 > best[i0]) { best[i0] = c1; bidx[i0] = k0 + 1; }
                if (c2 > best[i1]) { best[i1] = c2; bidx[i1] = k0; }
                if (c3 > best[i1]) { best[i1] = c3; bidx[i1] = k0 + 1; }
            }
        }
        __syncthreads();
    }

    // Cross-lane/warp argmax (scratch overlays dead B0; RAW/AH stay live)
    float* red_s = (float*)(smem + SM_REDS);
    int*   red_i = (int*)(smem + SM_REDI);
    float* lsum  = (float*)(smem + SM_LSUM);
    const int e = warp_n * 4 + (l & 3);
    #pragma unroll
    for (int mi = 0; mi < 4; mi++) {
        #pragma unroll
        for (int h = 0; h < 2; h++) {
            int row = warp_m * 64 + mi * 16 + (l >> 2) + h * 8;
            red_s[row * 16 + e] = best[mi * 2 + h];
            red_i[row * 16 + e] = bidx[mi * 2 + h];
        }
    }
    __syncthreads();
    if (tid < TM) {
        float bs = -1e30f; int bk = 0;
        #pragma unroll
        for (int q = 0; q < 16; q++) {
            float s = red_s[tid * 16 + q];
            int   k = red_i[tid * 16 + q];
            if (s > bs || (s == bs && k < bk)) { bs = s; bk = k; }
        }
        // EXACT loss: dot raw fp32 feature row (smem) with raw fp32 center row
        const float4* raw4 = (const float4*)(smem + SM_RAW + tid * 512);
        const float4* crow = (const float4*)(centers + (size_t)bk * D);
        float rinv = ((float*)(smem + SM_RINV))[tid];
        float dot = 0.0f;
        #pragma unroll
        for (int j = 0; j < 32; j++) {
            int i4 = (j + tid) & 31;
            float4 a = raw4[i4];
            float4 c = crow[i4];
            dot += a.x * c.x + a.y * c.y + a.z * c.z + a.w * c.w;
        }
        lsum[tid] = 1.0f + g_cnormsq[bk] - 2.0f * rinv * dot;
    }
    __syncthreads();
    #pragma unroll
    for (int s = TM / 2; s > 0; s >>= 1) {
        if (tid < s) lsum[tid] += lsum[tid + s];
        __syncthreads();
    }

    __shared__ unsigned int is_last;
    if (tid == 0) {
        g_partial[blockIdx.x] = lsum[0];
        __threadfence();
        is_last = (atomicAdd(&g_ctr, 1u) == NBLK - 1u);
    }
    __syncthreads();

    // Last-arriving block: deterministic fixed-order final reduction
    if (is_last) {
        __threadfence();
        double* sd = (double*)(smem + SM_B0);
        double s = 0.0;
        for (int i = tid; i < NBLK; i += 256)
            s += (double)(*(volatile float*)&g_partial[i]);
        sd[tid] = s;
        __syncthreads();
        for (int st = 128; st > 0; st >>= 1) {
            if (tid < st) sd[tid] += sd[tid + st];
            __syncthreads();
        }
        if (tid == 0) {
            out[0] = (float)(sd[0] / (double)N_FEAT);
            g_ctr = 0;   // reset for next graph replay
        }
    }
}

extern "C" void kernel_launch(void* const* d_in, const int* in_sizes, int n_in,
                              void* d_out, int out_size) {
    const float* features = (const float*)d_in[0];
    const float* centers  = (const float*)d_in[1];
    float* out = (float*)d_out;

    cudaFuncSetAttribute(gemm_argmax_mma,
                         cudaFuncAttributeMaxDynamicSharedMemorySize, SMEM_TOTAL);

    prep_centers<<<K, D>>>(centers);
    gemm_argmax_mma<<<NBLK, 256, SMEM_TOTAL>>>(features, centers, out);
}

// round 7
// speedup vs baseline: 1.0979x; 1.0979x over previous
#include <cuda_runtime.h>
#include <cuda_bf16.h>
#include <cstdint>
#include <math.h>

// ---------------------------------------------------------------------------
// Problem constants
// ---------------------------------------------------------------------------
#define N_FEAT 131072
#define D      128
#define K      1024
#define TM     64             // rows per CTA
#define TN     128            // centers per B-tile
#define NTILE  (K / TN)       // 8
#define NBLK   (N_FEAT / TM)  // 2048

#define RAW_BYTES (TM * D * 4)     // 32768 raw fp32 rows
#define A_BYTES   (TM * D * 2)     // 16384 bf16-hi tile (256B rows)
#define B_BYTES   (TN * D * 2)     // 32768 per B tile

// SMEM map (dynamic): total 115712 -> 2 CTAs/SM
#define SM_CTRL 0
#define SM_RINV 256
#define SM_RAW  1024
#define SM_AH   (SM_RAW + RAW_BYTES)
#define SM_B0   (SM_AH + A_BYTES)
#define SM_B1   (SM_B0 + B_BYTES)
#define SMEM_TOTAL (SM_B1 + B_BYTES)   // 115712
// epilogue scratch overlays the (dead) B0 region
#define SM_REDS SM_B0
#define SM_REDI (SM_B0 + 4096)
#define SM_BKS  (SM_B0 + 8192)
#define SM_LSUM (SM_B0 + 8448)
#define SM_SD   (SM_B0 + 9216)

#define MB_RAW 0
#define MB_B0  8
#define MB_B1  16

// ---------------------------------------------------------------------------
// Device scratch
// ---------------------------------------------------------------------------
__device__ __align__(1024) unsigned char g_B[NTILE * B_BYTES];  // 256 KB
__device__ float g_cnormsq[K];
__device__ float g_partial[NBLK];
__device__ unsigned int g_ctr;

// ---------------------------------------------------------------------------
// PTX helpers
// ---------------------------------------------------------------------------
__device__ __forceinline__ uint32_t smem_u32(const void* p) {
    uint32_t a;
    asm("{ .reg .u64 t; cvta.to.shared.u64 t, %1; cvt.u32.u64 %0, t; }" : "=r"(a) : "l"(p));
    return a;
}
#define MBAR_INIT(a, c) \
    asm volatile("mbarrier.init.shared.b64 [%0], %1;" :: "r"((uint32_t)(a)), "r"((uint32_t)(c)) : "memory")
#define MBAR_EXPECT_TX(a, b) \
    asm volatile("mbarrier.arrive.expect_tx.shared.b64 _, [%0], %1;" :: "r"((uint32_t)(a)), "r"((uint32_t)(b)) : "memory")
#define MBAR_WAIT(a, ph) do { \
    uint32_t _m = (uint32_t)(a), _p = (uint32_t)(ph), _d; \
    asm volatile("{ .reg .pred p; mbarrier.try_wait.parity.acquire.cta.shared::cta.b64 p, [%1], %2; selp.b32 %0,1,0,p; }" \
        : "=r"(_d) : "r"(_m), "r"(_p) : "memory"); \
    if (!_d) { \
        asm volatile("{ .reg .pred P1; WL%=: mbarrier.try_wait.parity.acquire.cta.shared::cta.b64 P1, [%0], %1, 0x989680; @P1 bra.uni WD%=; bra.uni WL%=; WD%=: }" \
            :: "r"(_m), "r"(_p) : "memory"); \
    } \
} while (0)

__device__ __forceinline__ void bulk_g2s(uint32_t dst, const void* src,
                                         uint32_t bytes, uint32_t mbar) {
    asm volatile(
        "cp.async.bulk.shared::cta.global.mbarrier::complete_tx::bytes [%0], [%1], %2, [%3];"
        :: "r"(dst), "l"(src), "r"(bytes), "r"(mbar) : "memory");
}
#define LDSM_X4(r, a) \
    asm volatile("ldmatrix.sync.aligned.m8n8.x4.shared.b16 {%0,%1,%2,%3}, [%4];" \
        : "=r"((r)[0]), "=r"((r)[1]), "=r"((r)[2]), "=r"((r)[3]) : "r"(a))
#define MMA_BF16(c, a, b0_, b1_) \
    asm volatile("mma.sync.aligned.m16n8k16.row.col.f32.bf16.bf16.f32 " \
        "{%0,%1,%2,%3}, {%4,%5,%6,%7}, {%8,%9}, {%0,%1,%2,%3};" \
        : "+f"((c)[0]), "+f"((c)[1]), "+f"((c)[2]), "+f"((c)[3]) \
        : "r"((a)[0]), "r"((a)[1]), "r"((a)[2]), "r"((a)[3]), "r"(b0_), "r"(b1_))

__device__ __forceinline__ unsigned short bf16_bits(__nv_bfloat16 h) {
    return *reinterpret_cast<unsigned short*>(&h);
}
__device__ __forceinline__ unsigned int pack_bf2(float a, float b) {
    return (unsigned)bf16_bits(__float2bfloat16(a)) |
           ((unsigned)bf16_bits(__float2bfloat16(b)) << 16);
}

// ---------------------------------------------------------------------------
// Prep: centers -> normalize; bf16-hi into g_B (unchanged layout from round 6)
// ---------------------------------------------------------------------------
__global__ void prep_centers(const float* __restrict__ centers) {
    int k = blockIdx.x;
    int d = threadIdx.x;
    float v = centers[k * D + d];
    float s = v * v;
    #pragma unroll
    for (int o = 16; o; o >>= 1) s += __shfl_down_sync(0xffffffffu, s, o);
    __shared__ float ws[4];
    if ((d & 31) == 0) ws[d >> 5] = s;
    __syncthreads();
    float tot  = ws[0] + ws[1] + ws[2] + ws[3];
    float norm = sqrtf(tot);
    float x = v / fmaxf(norm, 1e-12f);
    unsigned char* tile = g_B + (size_t)(k >> 7) * B_BYTES;
    int nn = k & 127;
    uint32_t off = (uint32_t)(nn * 256 + ((((d >> 3) ^ (nn & 7)) & 15) << 4) + (d & 7) * 2);
    *(unsigned short*)(tile + off) = bf16_bits(__float2bfloat16(x));
    if (d == 0) g_cnormsq[k] = tot;
}

// ---------------------------------------------------------------------------
// Main kernel: TM=64, 2 CTAs/SM; warp tile 32x32
// ---------------------------------------------------------------------------
__global__ __launch_bounds__(256, 2)
void gemm_argmax_mma(const float* __restrict__ features,
                     const float* __restrict__ centers,
                     float* __restrict__ out) {
    extern __shared__ __align__(1024) unsigned char smem[];
    uint32_t sb = smem_u32(smem);
    const int tid = threadIdx.x;
    const int wid = tid >> 5, l = tid & 31;
    const int warp_m = wid >> 2, warp_n = wid & 3;

    if (tid == 0) {
        MBAR_INIT(sb + SM_CTRL + MB_RAW, 1);
        MBAR_INIT(sb + SM_CTRL + MB_B0, 1);
        MBAR_INIT(sb + SM_CTRL + MB_B1, 1);
    }
    __syncthreads();
    if (tid == 0) {
        MBAR_EXPECT_TX(sb + SM_CTRL + MB_RAW, RAW_BYTES);
        bulk_g2s(sb + SM_RAW, features + (size_t)blockIdx.x * TM * D,
                 RAW_BYTES, sb + SM_CTRL + MB_RAW);
        MBAR_EXPECT_TX(sb + SM_CTRL + MB_B0, B_BYTES);
        bulk_g2s(sb + SM_B0, g_B, B_BYTES, sb + SM_CTRL + MB_B0);
        MBAR_EXPECT_TX(sb + SM_CTRL + MB_B1, B_BYTES);
        bulk_g2s(sb + SM_B1, g_B + B_BYTES, B_BYTES, sb + SM_CTRL + MB_B1);
    }

    // ---- A prep: 4 threads per row ----
    MBAR_WAIT(sb + SM_CTRL + MB_RAW, 0);
    {
        const int row = tid >> 2, q = tid & 3;
        const float4* raw4 = (const float4*)(smem + SM_RAW + row * 512);
        float s = 0.0f;
        #pragma unroll
        for (int j = 0; j < 8; j++) {
            float4 v = raw4[q * 8 + ((j + row) & 7)];
            s += v.x * v.x + v.y * v.y + v.z * v.z + v.w * v.w;
        }
        s += __shfl_xor_sync(0xffffffffu, s, 1);
        s += __shfl_xor_sync(0xffffffffu, s, 2);
        float rinv = 1.0f / fmaxf(sqrtf(s), 1e-12f);
        if (q == 0) ((float*)(smem + SM_RINV))[row] = rinv;
        unsigned char* arow = smem + SM_AH + row * 256;
        #pragma unroll
        for (int cc = 0; cc < 4; cc++) {
            int c = q * 4 + cc;                 // logical chunk: dims c*8..c*8+7
            float4 a0 = raw4[c * 2];
            float4 a1 = raw4[c * 2 + 1];
            uint4 o;
            o.x = pack_bf2(a0.x * rinv, a0.y * rinv);
            o.y = pack_bf2(a0.z * rinv, a0.w * rinv);
            o.z = pack_bf2(a1.x * rinv, a1.y * rinv);
            o.w = pack_bf2(a1.z * rinv, a1.w * rinv);
            int fc = c ^ (row & 7);
            *(uint4*)(arow + (fc << 4)) = o;
        }
    }
    __syncthreads();

    const int a_row_in = (l & 7) + ((l >> 3) & 1) * 8;
    const int a_cb     = (l >> 4);
    const int b_row_in = (l & 7) + ((l >> 4) & 1) * 8;
    const int b_cb     = (l >> 3) & 1;

    float best[4];
    int   bidx[4];
    #pragma unroll
    for (int i = 0; i < 4; i++) { best[i] = -1e30f; bidx[i] = 0; }

    for (int t = 0; t < NTILE; t++) {
        const uint32_t bbuf = (t & 1) ? (sb + SM_B1) : (sb + SM_B0);
        MBAR_WAIT(sb + SM_CTRL + ((t & 1) ? MB_B1 : MB_B0), (t >> 1) & 1);

        float acc[2][4][4];
        #pragma unroll
        for (int mi = 0; mi < 2; mi++)
            #pragma unroll
            for (int ni = 0; ni < 4; ni++)
                #pragma unroll
                for (int e2 = 0; e2 < 4; e2++) acc[mi][ni][e2] = 0.0f;

        #pragma unroll
        for (int kk = 0; kk < 8; kk++) {
            uint32_t af[2][4];
            #pragma unroll
            for (int mi = 0; mi < 2; mi++) {
                int row = warp_m * 32 + mi * 16 + a_row_in;
                uint32_t addr = sb + SM_AH + row * 256 +
                                (((kk * 2 + a_cb) ^ (row & 7)) << 4);
                LDSM_X4(af[mi], addr);
            }
            uint32_t bfm[2][4];
            #pragma unroll
            for (int bp = 0; bp < 2; bp++) {
                int nrow = warp_n * 32 + bp * 16 + b_row_in;
                uint32_t addr = bbuf + nrow * 256 +
                                (((kk * 2 + b_cb) ^ (nrow & 7)) << 4);
                LDSM_X4(bfm[bp], addr);
            }
            #pragma unroll
            for (int mi = 0; mi < 2; mi++)
                #pragma unroll
                for (int ni = 0; ni < 4; ni++)
                    MMA_BF16(acc[mi][ni], af[mi],
                             bfm[ni >> 1][(ni & 1) * 2], bfm[ni >> 1][(ni & 1) * 2 + 1]);
        }

        #pragma unroll
        for (int mi = 0; mi < 2; mi++) {
            #pragma unroll
            for (int ni = 0; ni < 4; ni++) {
                int k0 = t * TN + warp_n * 32 + ni * 8 + (l & 3) * 2;
                float c0 = acc[mi][ni][0], c1 = acc[mi][ni][1];
                float c2 = acc[mi][ni][2], c3 = acc[mi][ni][3];
                int i0 = mi * 2, i1 = mi * 2 + 1;
                if (c0 > best[i0]) { best[i0] = c0; bidx[i0] = k0; }
                if (c1 > best[i0]) { best[i0] = c1; bidx[i0] = k0 + 1; }
                if (c2 > best[i1]) { best[i1] = c2; bidx[i1] = k0; }
                if (c3 > best[i1]) { best[i1] = c3; bidx[i1] = k0 + 1; }
            }
        }
        __syncthreads();
        if (tid == 0 && t + 2 < NTILE) {
            uint32_t mb = sb + SM_CTRL + ((t & 1) ? MB_B1 : MB_B0);
            MBAR_EXPECT_TX(mb, B_BYTES);
            bulk_g2s(bbuf, g_B + (size_t)(t + 2) * B_BYTES, B_BYTES, mb);
        }
    }

    float* red_s = (float*)(smem + SM_REDS);
    int*   red_i = (int*)(smem + SM_REDI);
    int*   bks   = (int*)(smem + SM_BKS);
    float* lsum  = (float*)(smem + SM_LSUM);
    const int e = warp_n * 4 + (l & 3);
    #pragma unroll
    for (int mi = 0; mi < 2; mi++) {
        #pragma unroll
        for (int h = 0; h < 2; h++) {
            int row = warp_m * 32 + mi * 16 + (l >> 2) + h * 8;
            red_s[row * 16 + e] = best[mi * 2 + h];
            red_i[row * 16 + e] = bidx[mi * 2 + h];
        }
    }
    __syncthreads();
    if (tid < TM) {
        float bs = -1e30f; int bk = 0;
        #pragma unroll
        for (int q = 0; q < 16; q++) {
            float s = red_s[tid * 16 + q];
            int   k = red_i[tid * 16 + q];
            if (s > bs || (s == bs && k < bk)) { bs = s; bk = k; }
        }
        bks[tid] = bk;
    }
    __syncthreads();
    {
        const int row = tid >> 2, q = tid & 3;
        const int bk  = bks[row];
        const float4* raw4 = (const float4*)(smem + SM_RAW + row * 512);
        const float4* crow = (const float4*)(centers + (size_t)bk * D);
        float dot = 0.0f;
        #pragma unroll
        for (int j = 0; j < 8; j++) {
            int i4 = q * 8 + ((j + row) & 7);
            float4 a = raw4[i4];
            float4 c = crow[i4];
            dot += a.x * c.x + a.y * c.y + a.z * c.z + a.w * c.w;
        }
        dot += __shfl_xor_sync(0xffffffffu, dot, 1);
        dot += __shfl_xor_sync(0xffffffffu, dot, 2);
        if (q == 0) {
            float rinv = ((float*)(smem + SM_RINV))[row];
            lsum[row] = 1.0f + g_cnormsq[bk] - 2.0f * rinv * dot;
        }
    }
    __syncthreads();
    #pragma unroll
    for (int s = TM / 2; s > 0; s >>= 1) {
        if (tid < s) lsum[tid] += lsum[tid + s];
        __syncthreads();
    }

    __shared__ unsigned int is_last;
    if (tid == 0) {
        g_partial[blockIdx.x] = lsum[0];
        __threadfence();
        is_last = (atomicAdd(&g_ctr, 1u) == NBLK - 1u);
    }
    __syncthreads();

    if (is_last) {
        __threadfence();
        double* sd = (double*)(smem + SM_SD);
        double s = 0.0;
        for (int i = tid; i < NBLK; i += 256)
            s += (double)(*(volatile float*)&g_partial[i]);
        sd[tid] = s;
        __syncthreads();
        for (int st = 128; st > 0; st >>= 1) {
            if (tid < st) sd[tid] += sd[tid + st];
            __syncthreads();
        }
        if (tid == 0) {
            out[0] = (float)(sd[0] / (double)N_FEAT);
            g_ctr = 0;
        }
    }
}

extern "C" void kernel_launch(void* const* d_in, const int* in_sizes, int n_in,
                              void* d_out, int out_size) {
    const float* features = (const float*)d_in[0];
    const float* centers  = (const float*)d_in[1];
    float* out = (float*)d_out;

    cudaFuncSetAttribute(gemm_argmax_mma,
                         cudaFuncAttributeMaxDynamicSharedMemorySize, SMEM_TOTAL);

    prep_centers<<<K, D>>>(centers);
    gemm_argmax_mma<<<NBLK, 256, SMEM_TOTAL>>>(features, centers, out);
}

// round 8
// speedup vs baseline: 1.3385x; 1.2191x over previous
#include <cuda_runtime.h>
#include <cuda_bf16.h>
#include <cstdint>
#include <math.h>

// ---------------------------------------------------------------------------
// Problem constants
// ---------------------------------------------------------------------------
#define N_FEAT 131072
#define D      128
#define K      1024
#define TM     64             // rows per CTA
#define TN     128            // centers per B-tile
#define NTILE  (K / TN)       // 8
#define NBLK   (N_FEAT / TM)  // 2048

#define RAW_BYTES (TM * D * 4)     // 32768 raw fp32 rows (staged transiently)
#define A_BYTES   (TM * D * 2)     // 16384 bf16-hi tile (256B rows)
#define B_BYTES   (TN * D * 2)     // 32768 per B tile

// SMEM map (dynamic): ctrl 1KB + AH 16KB + B0 32KB + B1 32KB = 82944 bytes
// -> ~90KB after granularity, 2 CTAs/SM fit in 228KB.
#define SM_CTRL 0
#define SM_RINV 256
#define SM_AH   1024
#define SM_B0   (SM_AH + A_BYTES)          // 17408; ALSO transient RAW staging
#define SM_B1   (SM_B0 + B_BYTES)          // 50176
#define SMEM_TOTAL (SM_B1 + B_BYTES)       // 82944
// epilogue scratch overlays the (dead) B0 region
#define SM_REDS SM_B0
#define SM_REDI (SM_B0 + 4096)
#define SM_BKS  (SM_B0 + 8192)
#define SM_LSUM (SM_B0 + 8448)
#define SM_SD   (SM_B0 + 9216)

#define MB_RAW 0
#define MB_B0  8
#define MB_B1  16

// ---------------------------------------------------------------------------
// Device scratch
// ---------------------------------------------------------------------------
__device__ __align__(1024) unsigned char g_B[NTILE * B_BYTES];  // 256 KB
__device__ float g_cnormsq[K];
__device__ float g_partial[NBLK];
__device__ unsigned int g_ctr;

// ---------------------------------------------------------------------------
// PTX helpers
// ---------------------------------------------------------------------------
__device__ __forceinline__ uint32_t smem_u32(const void* p) {
    uint32_t a;
    asm("{ .reg .u64 t; cvta.to.shared.u64 t, %1; cvt.u32.u64 %0, t; }" : "=r"(a) : "l"(p));
    return a;
}
#define MBAR_INIT(a, c) \
    asm volatile("mbarrier.init.shared.b64 [%0], %1;" :: "r"((uint32_t)(a)), "r"((uint32_t)(c)) : "memory")
#define MBAR_EXPECT_TX(a, b) \
    asm volatile("mbarrier.arrive.expect_tx.shared.b64 _, [%0], %1;" :: "r"((uint32_t)(a)), "r"((uint32_t)(b)) : "memory")
#define MBAR_WAIT(a, ph) do { \
    uint32_t _m = (uint32_t)(a), _p = (uint32_t)(ph), _d; \
    asm volatile("{ .reg .pred p; mbarrier.try_wait.parity.acquire.cta.shared::cta.b64 p, [%1], %2; selp.b32 %0,1,0,p; }" \
        : "=r"(_d) : "r"(_m), "r"(_p) : "memory"); \
    if (!_d) { \
        asm volatile("{ .reg .pred P1; WL%=: mbarrier.try_wait.parity.acquire.cta.shared::cta.b64 P1, [%0], %1, 0x989680; @P1 bra.uni WD%=; bra.uni WL%=; WD%=: }" \
            :: "r"(_m), "r"(_p) : "memory"); \
    } \
} while (0)

__device__ __forceinline__ void bulk_g2s(uint32_t dst, const void* src,
                                         uint32_t bytes, uint32_t mbar) {
    asm volatile(
        "cp.async.bulk.shared::cta.global.mbarrier::complete_tx::bytes [%0], [%1], %2, [%3];"
        :: "r"(dst), "l"(src), "r"(bytes), "r"(mbar) : "memory");
}
#define LDSM_X4(r, a) \
    asm volatile("ldmatrix.sync.aligned.m8n8.x4.shared.b16 {%0,%1,%2,%3}, [%4];" \
        : "=r"((r)[0]), "=r"((r)[1]), "=r"((r)[2]), "=r"((r)[3]) : "r"(a))
#define MMA_BF16(c, a, b0_, b1_) \
    asm volatile("mma.sync.aligned.m16n8k16.row.col.f32.bf16.bf16.f32 " \
        "{%0,%1,%2,%3}, {%4,%5,%6,%7}, {%8,%9}, {%0,%1,%2,%3};" \
        : "+f"((c)[0]), "+f"((c)[1]), "+f"((c)[2]), "+f"((c)[3]) \
        : "r"((a)[0]), "r"((a)[1]), "r"((a)[2]), "r"((a)[3]), "r"(b0_), "r"(b1_))

__device__ __forceinline__ unsigned short bf16_bits(__nv_bfloat16 h) {
    return *reinterpret_cast<unsigned short*>(&h);
}
__device__ __forceinline__ unsigned int pack_bf2(float a, float b) {
    return (unsigned)bf16_bits(__float2bfloat16(a)) |
           ((unsigned)bf16_bits(__float2bfloat16(b)) << 16);
}

// ---------------------------------------------------------------------------
// Prep: centers -> normalize; bf16-hi into g_B (layout unchanged)
// ---------------------------------------------------------------------------
__global__ void prep_centers(const float* __restrict__ centers) {
    int k = blockIdx.x;
    int d = threadIdx.x;
    float v = centers[k * D + d];
    float s = v * v;
    #pragma unroll
    for (int o = 16; o; o >>= 1) s += __shfl_down_sync(0xffffffffu, s, o);
    __shared__ float ws[4];
    if ((d & 31) == 0) ws[d >> 5] = s;
    __syncthreads();
    float tot  = ws[0] + ws[1] + ws[2] + ws[3];
    float norm = sqrtf(tot);
    float x = v / fmaxf(norm, 1e-12f);
    unsigned char* tile = g_B + (size_t)(k >> 7) * B_BYTES;
    int nn = k & 127;
    uint32_t off = (uint32_t)(nn * 256 + ((((d >> 3) ^ (nn & 7)) & 15) << 4) + (d & 7) * 2);
    *(unsigned short*)(tile + off) = bf16_bits(__float2bfloat16(x));
    if (d == 0) g_cnormsq[k] = tot;
}

// ---------------------------------------------------------------------------
// Main kernel: TM=64, slim smem -> 2 CTAs/SM; warp tile 32x32
// ---------------------------------------------------------------------------
__global__ __launch_bounds__(256, 2)
void gemm_argmax_mma(const float* __restrict__ features,
                     const float* __restrict__ centers,
                     float* __restrict__ out) {
    extern __shared__ __align__(1024) unsigned char smem[];
    uint32_t sb = smem_u32(smem);
    const int tid = threadIdx.x;
    const int wid = tid >> 5, l = tid & 31;
    const int warp_m = wid >> 2, warp_n = wid & 3;

    if (tid == 0) {
        MBAR_INIT(sb + SM_CTRL + MB_RAW, 1);
        MBAR_INIT(sb + SM_CTRL + MB_B0, 1);
        MBAR_INIT(sb + SM_CTRL + MB_B1, 1);
    }
    __syncthreads();
    // Stage raw fp32 rows into the (not-yet-used) B0 region
    if (tid == 0) {
        MBAR_EXPECT_TX(sb + SM_CTRL + MB_RAW, RAW_BYTES);
        bulk_g2s(sb + SM_B0, features + (size_t)blockIdx.x * TM * D,
                 RAW_BYTES, sb + SM_CTRL + MB_RAW);
    }

    // ---- A prep: 4 threads per row, raw read from B0 staging ----
    MBAR_WAIT(sb + SM_CTRL + MB_RAW, 0);
    {
        const int row = tid >> 2, q = tid & 3;
        const float4* raw4 = (const float4*)(smem + SM_B0 + row * 512);
        float s = 0.0f;
        #pragma unroll
        for (int j = 0; j < 8; j++) {
            float4 v = raw4[q * 8 + ((j + row) & 7)];
            s += v.x * v.x + v.y * v.y + v.z * v.z + v.w * v.w;
        }
        s += __shfl_xor_sync(0xffffffffu, s, 1);
        s += __shfl_xor_sync(0xffffffffu, s, 2);
        float rinv = 1.0f / fmaxf(sqrtf(s), 1e-12f);
        if (q == 0) ((float*)(smem + SM_RINV))[row] = rinv;
        unsigned char* arow = smem + SM_AH + row * 256;
        #pragma unroll
        for (int cc = 0; cc < 4; cc++) {
            int c = q * 4 + cc;                 // logical chunk: dims c*8..c*8+7
            float4 a0 = raw4[c * 2];
            float4 a1 = raw4[c * 2 + 1];
            uint4 o;
            o.x = pack_bf2(a0.x * rinv, a0.y * rinv);
            o.y = pack_bf2(a0.z * rinv, a0.w * rinv);
            o.z = pack_bf2(a1.x * rinv, a1.y * rinv);
            o.w = pack_bf2(a1.z * rinv, a1.w * rinv);
            int fc = c ^ (row & 7);
            *(uint4*)(arow + (fc << 4)) = o;
        }
    }
    __syncthreads();   // all raw reads done; B0 region reusable

    // Kick both B buffers
    if (tid == 0) {
        MBAR_EXPECT_TX(sb + SM_CTRL + MB_B0, B_BYTES);
        bulk_g2s(sb + SM_B0, g_B, B_BYTES, sb + SM_CTRL + MB_B0);
        MBAR_EXPECT_TX(sb + SM_CTRL + MB_B1, B_BYTES);
        bulk_g2s(sb + SM_B1, g_B + B_BYTES, B_BYTES, sb + SM_CTRL + MB_B1);
    }

    const int a_row_in = (l & 7) + ((l >> 3) & 1) * 8;
    const int a_cb     = (l >> 4);
    const int b_row_in = (l & 7) + ((l >> 4) & 1) * 8;
    const int b_cb     = (l >> 3) & 1;

    float best[4];
    int   bidx[4];
    #pragma unroll
    for (int i = 0; i < 4; i++) { best[i] = -1e30f; bidx[i] = 0; }

    for (int t = 0; t < NTILE; t++) {
        const uint32_t bbuf = (t & 1) ? (sb + SM_B1) : (sb + SM_B0);
        MBAR_WAIT(sb + SM_CTRL + ((t & 1) ? MB_B1 : MB_B0), (t >> 1) & 1);

        float acc[2][4][4];
        #pragma unroll
        for (int mi = 0; mi < 2; mi++)
            #pragma unroll
            for (int ni = 0; ni < 4; ni++)
                #pragma unroll
                for (int e2 = 0; e2 < 4; e2++) acc[mi][ni][e2] = 0.0f;

        #pragma unroll
        for (int kk = 0; kk < 8; kk++) {
            uint32_t af[2][4];
            #pragma unroll
            for (int mi = 0; mi < 2; mi++) {
                int row = warp_m * 32 + mi * 16 + a_row_in;
                uint32_t addr = sb + SM_AH + row * 256 +
                                (((kk * 2 + a_cb) ^ (row & 7)) << 4);
                LDSM_X4(af[mi], addr);
            }
            uint32_t bfm[2][4];
            #pragma unroll
            for (int bp = 0; bp < 2; bp++) {
                int nrow = warp_n * 32 + bp * 16 + b_row_in;
                uint32_t addr = bbuf + nrow * 256 +
                                (((kk * 2 + b_cb) ^ (nrow & 7)) << 4);
                LDSM_X4(bfm[bp], addr);
            }
            #pragma unroll
            for (int mi = 0; mi < 2; mi++)
                #pragma unroll
                for (int ni = 0; ni < 4; ni++)
                    MMA_BF16(acc[mi][ni], af[mi],
                             bfm[ni >> 1][(ni & 1) * 2], bfm[ni >> 1][(ni & 1) * 2 + 1]);
        }

        #pragma unroll
        for (int mi = 0; mi < 2; mi++) {
            #pragma unroll
            for (int ni = 0; ni < 4; ni++) {
                int k0 = t * TN + warp_n * 32 + ni * 8 + (l & 3) * 2;
                float c0 = acc[mi][ni][0], c1 = acc[mi][ni][1];
                float c2 = acc[mi][ni][2], c3 = acc[mi][ni][3];
                int i0 = mi * 2, i1 = mi * 2 + 1;
                if (c0 > best[i0]) { best[i0] = c0; bidx[i0] = k0; }
                if (c1 > best[i0]) { best[i0] = c1; bidx[i0] = k0 + 1; }
                if (c2 > best[i1]) { best[i1] = c2; bidx[i1] = k0; }
                if (c3 > best[i1]) { best[i1] = c3; bidx[i1] = k0 + 1; }
            }
        }
        __syncthreads();
        if (tid == 0 && t + 2 < NTILE) {
            uint32_t mb = sb + SM_CTRL + ((t & 1) ? MB_B1 : MB_B0);
            MBAR_EXPECT_TX(mb, B_BYTES);
            bulk_g2s(bbuf, g_B + (size_t)(t + 2) * B_BYTES, B_BYTES, mb);
        }
    }

    float* red_s = (float*)(smem + SM_REDS);
    int*   red_i = (int*)(smem + SM_REDI);
    int*   bks   = (int*)(smem + SM_BKS);
    float* lsum  = (float*)(smem + SM_LSUM);
    const int e = warp_n * 4 + (l & 3);
    #pragma unroll
    for (int mi = 0; mi < 2; mi++) {
        #pragma unroll
        for (int h = 0; h < 2; h++) {
            int row = warp_m * 32 + mi * 16 + (l >> 2) + h * 8;
            red_s[row * 16 + e] = best[mi * 2 + h];
            red_i[row * 16 + e] = bidx[mi * 2 + h];
        }
    }
    __syncthreads();
    if (tid < TM) {
        float bs = -1e30f; int bk = 0;
        #pragma unroll
        for (int q = 0; q < 16; q++) {
            float s = red_s[tid * 16 + q];
            int   k = red_i[tid * 16 + q];
            if (s > bs || (s == bs && k < bk)) { bs = s; bk = k; }
        }
        bks[tid] = bk;
    }
    __syncthreads();
    // EXACT loss: 4 threads/row; features re-read from global (L2/HBM)
    {
        const int row = tid >> 2, q = tid & 3;
        const int bk  = bks[row];
        const float4* frow = (const float4*)(features + (size_t)(blockIdx.x * TM + row) * D);
        const float4* crow = (const float4*)(centers + (size_t)bk * D);
        float dot = 0.0f;
        #pragma unroll
        for (int j = 0; j < 8; j++) {
            int i4 = q * 8 + j;
            float4 a = frow[i4];
            float4 c = crow[i4];
            dot += a.x * c.x + a.y * c.y + a.z * c.z + a.w * c.w;
        }
        dot += __shfl_xor_sync(0xffffffffu, dot, 1);
        dot += __shfl_xor_sync(0xffffffffu, dot, 2);
        if (q == 0) {
            float rinv = ((float*)(smem + SM_RINV))[row];
            lsum[row] = 1.0f + g_cnormsq[bk] - 2.0f * rinv * dot;
        }
    }
    __syncthreads();
    #pragma unroll
    for (int s = TM / 2; s > 0; s >>= 1) {
        if (tid < s) lsum[tid] += lsum[tid + s];
        __syncthreads();
    }

    __shared__ unsigned int is_last;
    if (tid == 0) {
        g_partial[blockIdx.x] = lsum[0];
        __threadfence();
        is_last = (atomicAdd(&g_ctr, 1u) == NBLK - 1u);
    }
    __syncthreads();

    if (is_last) {
        __threadfence();
        double* sd = (double*)(smem + SM_SD);
        double s = 0.0;
        for (int i = tid; i < NBLK; i += 256)
            s += (double)(*(volatile float*)&g_partial[i]);
        sd[tid] = s;
        __syncthreads();
        for (int st = 128; st > 0; st >>= 1) {
            if (tid < st) sd[tid] += sd[tid + st];
            __syncthreads();
        }
        if (tid == 0) {
            out[0] = (float)(sd[0] / (double)N_FEAT);
            g_ctr = 0;
        }
    }
}

extern "C" void kernel_launch(void* const* d_in, const int* in_sizes, int n_in,
                              void* d_out, int out_size) {
    const float* features = (const float*)d_in[0];
    const float* centers  = (const float*)d_in[1];
    float* out = (float*)d_out;

    cudaFuncSetAttribute(gemm_argmax_mma,
                         cudaFuncAttributeMaxDynamicSharedMemorySize, SMEM_TOTAL);

    prep_centers<<<K, D>>>(centers);
    gemm_argmax_mma<<<NBLK, 256, SMEM_TOTAL>>>(features, centers, out);
}

// round 9
// speedup vs baseline: 1.4364x; 1.0731x over previous
#include <cuda_runtime.h>
#include <cuda_bf16.h>
#include <cstdint>
#include <math.h>

// ---------------------------------------------------------------------------
// Problem constants
// ---------------------------------------------------------------------------
#define N_FEAT 131072
#define D      128
#define K      1024
#define TM     64             // rows per CTA
#define TN     128            // centers per B-tile
#define NTILE  (K / TN)       // 8
#define NBLK   (N_FEAT / TM)  // 2048

#define RAW_BYTES (TM * D * 4)     // 32768 raw fp32 rows (staged transiently)
#define A_BYTES   (TM * D * 2)     // 16384 bf16-hi tile (256B rows)
#define B_BYTES   (TN * D * 2)     // 32768 per B tile

// SMEM map (dynamic): ctrl 1KB + AH 16KB + B0 32KB + B1 32KB = 82944 bytes
#define SM_CTRL 0
#define SM_RINV 256
#define SM_AH   1024
#define SM_B0   (SM_AH + A_BYTES)          // 17408; ALSO transient RAW staging
#define SM_B1   (SM_B0 + B_BYTES)          // 50176
#define SMEM_TOTAL (SM_B1 + B_BYTES)       // 82944
// epilogue scratch overlays the (dead) B0 region
#define SM_REDS SM_B0
#define SM_REDI (SM_B0 + 4096)
#define SM_BKS  (SM_B0 + 8192)
#define SM_LSUM (SM_B0 + 8448)
#define SM_SD   (SM_B0 + 9216)

#define MB_RAW 0
#define MB_B0  8
#define MB_B1  16

// ---------------------------------------------------------------------------
// Device scratch
// ---------------------------------------------------------------------------
__device__ __align__(1024) unsigned char g_B[NTILE * B_BYTES];  // 256 KB
__device__ float g_cnormsq[K];
__device__ float g_partial[NBLK];
__device__ unsigned int g_ctr;

// ---------------------------------------------------------------------------
// PTX helpers
// ---------------------------------------------------------------------------
__device__ __forceinline__ uint32_t smem_u32(const void* p) {
    uint32_t a;
    asm("{ .reg .u64 t; cvta.to.shared.u64 t, %1; cvt.u32.u64 %0, t; }" : "=r"(a) : "l"(p));
    return a;
}
#define MBAR_INIT(a, c) \
    asm volatile("mbarrier.init.shared.b64 [%0], %1;" :: "r"((uint32_t)(a)), "r"((uint32_t)(c)) : "memory")
#define MBAR_EXPECT_TX(a, b) \
    asm volatile("mbarrier.arrive.expect_tx.shared.b64 _, [%0], %1;" :: "r"((uint32_t)(a)), "r"((uint32_t)(b)) : "memory")
#define MBAR_WAIT(a, ph) do { \
    uint32_t _m = (uint32_t)(a), _p = (uint32_t)(ph), _d; \
    asm volatile("{ .reg .pred p; mbarrier.try_wait.parity.acquire.cta.shared::cta.b64 p, [%1], %2; selp.b32 %0,1,0,p; }" \
        : "=r"(_d) : "r"(_m), "r"(_p) : "memory"); \
    if (!_d) { \
        asm volatile("{ .reg .pred P1; WL%=: mbarrier.try_wait.parity.acquire.cta.shared::cta.b64 P1, [%0], %1, 0x989680; @P1 bra.uni WD%=; bra.uni WL%=; WD%=: }" \
            :: "r"(_m), "r"(_p) : "memory"); \
    } \
} while (0)

__device__ __forceinline__ void bulk_g2s(uint32_t dst, const void* src,
                                         uint32_t bytes, uint32_t mbar) {
    asm volatile(
        "cp.async.bulk.shared::cta.global.mbarrier::complete_tx::bytes [%0], [%1], %2, [%3];"
        :: "r"(dst), "l"(src), "r"(bytes), "r"(mbar) : "memory");
}
#define LDSM_X4(r, a) \
    asm volatile("ldmatrix.sync.aligned.m8n8.x4.shared.b16 {%0,%1,%2,%3}, [%4];" \
        : "=r"((r)[0]), "=r"((r)[1]), "=r"((r)[2]), "=r"((r)[3]) : "r"(a))
#define MMA_BF16(c, a, b0_, b1_) \
    asm volatile("mma.sync.aligned.m16n8k16.row.col.f32.bf16.bf16.f32 " \
        "{%0,%1,%2,%3}, {%4,%5,%6,%7}, {%8,%9}, {%0,%1,%2,%3};" \
        : "+f"((c)[0]), "+f"((c)[1]), "+f"((c)[2]), "+f"((c)[3]) \
        : "r"((a)[0]), "r"((a)[1]), "r"((a)[2]), "r"((a)[3]), "r"(b0_), "r"(b1_))

__device__ __forceinline__ unsigned short bf16_bits(__nv_bfloat16 h) {
    return *reinterpret_cast<unsigned short*>(&h);
}
__device__ __forceinline__ unsigned int pack_bf2(float a, float b) {
    return (unsigned)bf16_bits(__float2bfloat16(a)) |
           ((unsigned)bf16_bits(__float2bfloat16(b)) << 16);
}

// ---------------------------------------------------------------------------
// Prep: centers -> normalize; bf16-hi into g_B (layout unchanged)
// ---------------------------------------------------------------------------
__global__ void prep_centers(const float* __restrict__ centers) {
    int k = blockIdx.x;
    int d = threadIdx.x;
    float v = centers[k * D + d];
    float s = v * v;
    #pragma unroll
    for (int o = 16; o; o >>= 1) s += __shfl_down_sync(0xffffffffu, s, o);
    __shared__ float ws[4];
    if ((d & 31) == 0) ws[d >> 5] = s;
    __syncthreads();
    float tot  = ws[0] + ws[1] + ws[2] + ws[3];
    float norm = sqrtf(tot);
    float x = v / fmaxf(norm, 1e-12f);
    unsigned char* tile = g_B + (size_t)(k >> 7) * B_BYTES;
    int nn = k & 127;
    uint32_t off = (uint32_t)(nn * 256 + ((((d >> 3) ^ (nn & 7)) & 15) << 4) + (d & 7) * 2);
    *(unsigned short*)(tile + off) = bf16_bits(__float2bfloat16(x));
    if (d == 0) g_cnormsq[k] = tot;
}

// ---------------------------------------------------------------------------
// Main kernel: TM=64, 2 CTAs/SM; A fragments hoisted to registers
// ---------------------------------------------------------------------------
__global__ __launch_bounds__(256, 2)
void gemm_argmax_mma(const float* __restrict__ features,
                     const float* __restrict__ centers,
                     float* __restrict__ out) {
    extern __shared__ __align__(1024) unsigned char smem[];
    uint32_t sb = smem_u32(smem);
    const int tid = threadIdx.x;
    const int wid = tid >> 5, l = tid & 31;
    const int warp_m = wid >> 2, warp_n = wid & 3;

    if (tid == 0) {
        MBAR_INIT(sb + SM_CTRL + MB_RAW, 1);
        MBAR_INIT(sb + SM_CTRL + MB_B0, 1);
        MBAR_INIT(sb + SM_CTRL + MB_B1, 1);
    }
    __syncthreads();
    // Stage raw fp32 rows into the (not-yet-used) B0 region
    if (tid == 0) {
        MBAR_EXPECT_TX(sb + SM_CTRL + MB_RAW, RAW_BYTES);
        bulk_g2s(sb + SM_B0, features + (size_t)blockIdx.x * TM * D,
                 RAW_BYTES, sb + SM_CTRL + MB_RAW);
    }

    // ---- A prep: 4 threads per row, raw read from B0 staging ----
    MBAR_WAIT(sb + SM_CTRL + MB_RAW, 0);
    {
        const int row = tid >> 2, q = tid & 3;
        const float4* raw4 = (const float4*)(smem + SM_B0 + row * 512);
        float s = 0.0f;
        #pragma unroll
        for (int j = 0; j < 8; j++) {
            float4 v = raw4[q * 8 + ((j + row) & 7)];
            s += v.x * v.x + v.y * v.y + v.z * v.z + v.w * v.w;
        }
        s += __shfl_xor_sync(0xffffffffu, s, 1);
        s += __shfl_xor_sync(0xffffffffu, s, 2);
        float rinv = 1.0f / fmaxf(sqrtf(s), 1e-12f);
        if (q == 0) ((float*)(smem + SM_RINV))[row] = rinv;
        unsigned char* arow = smem + SM_AH + row * 256;
        #pragma unroll
        for (int cc = 0; cc < 4; cc++) {
            int c = q * 4 + cc;
            float4 a0 = raw4[c * 2];
            float4 a1 = raw4[c * 2 + 1];
            uint4 o;
            o.x = pack_bf2(a0.x * rinv, a0.y * rinv);
            o.y = pack_bf2(a0.z * rinv, a0.w * rinv);
            o.z = pack_bf2(a1.x * rinv, a1.y * rinv);
            o.w = pack_bf2(a1.z * rinv, a1.w * rinv);
            int fc = c ^ (row & 7);
            *(uint4*)(arow + (fc << 4)) = o;
        }
    }
    __syncthreads();   // all raw reads done; B0 region reusable

    // Kick both B buffers
    if (tid == 0) {
        MBAR_EXPECT_TX(sb + SM_CTRL + MB_B0, B_BYTES);
        bulk_g2s(sb + SM_B0, g_B, B_BYTES, sb + SM_CTRL + MB_B0);
        MBAR_EXPECT_TX(sb + SM_CTRL + MB_B1, B_BYTES);
        bulk_g2s(sb + SM_B1, g_B + B_BYTES, B_BYTES, sb + SM_CTRL + MB_B1);
    }

    const int a_row_in = (l & 7) + ((l >> 3) & 1) * 8;
    const int a_cb     = (l >> 4);
    const int b_row_in = (l & 7) + ((l >> 4) & 1) * 8;
    const int b_cb     = (l >> 3) & 1;

    // ---- Hoist ALL A fragments into registers (invariant across tiles) ----
    uint32_t afr[8][2][4];   // [kk][mi][frag]
    #pragma unroll
    for (int kk = 0; kk < 8; kk++) {
        #pragma unroll
        for (int mi = 0; mi < 2; mi++) {
            int row = warp_m * 32 + mi * 16 + a_row_in;
            uint32_t addr = sb + SM_AH + row * 256 +
                            (((kk * 2 + a_cb) ^ (row & 7)) << 4);
            LDSM_X4(afr[kk][mi], addr);
        }
    }

    float best[4];
    int   bidx[4];
    #pragma unroll
    for (int i = 0; i < 4; i++) { best[i] = -1e30f; bidx[i] = 0; }

    for (int t = 0; t < NTILE; t++) {
        const uint32_t bbuf = (t & 1) ? (sb + SM_B1) : (sb + SM_B0);
        MBAR_WAIT(sb + SM_CTRL + ((t & 1) ? MB_B1 : MB_B0), (t >> 1) & 1);

        float acc[2][4][4];
        #pragma unroll
        for (int mi = 0; mi < 2; mi++)
            #pragma unroll
            for (int ni = 0; ni < 4; ni++)
                #pragma unroll
                for (int e2 = 0; e2 < 4; e2++) acc[mi][ni][e2] = 0.0f;

        #pragma unroll
        for (int kk = 0; kk < 8; kk++) {
            uint32_t bfm[2][4];
            #pragma unroll
            for (int bp = 0; bp < 2; bp++) {
                int nrow = warp_n * 32 + bp * 16 + b_row_in;
                uint32_t addr = bbuf + nrow * 256 +
                                (((kk * 2 + b_cb) ^ (nrow & 7)) << 4);
                LDSM_X4(bfm[bp], addr);
            }
            #pragma unroll
            for (int mi = 0; mi < 2; mi++)
                #pragma unroll
                for (int ni = 0; ni < 4; ni++)
                    MMA_BF16(acc[mi][ni], afr[kk][mi],
                             bfm[ni >> 1][(ni & 1) * 2], bfm[ni >> 1][(ni & 1) * 2 + 1]);
        }

        #pragma unroll
        for (int mi = 0; mi < 2; mi++) {
            #pragma unroll
            for (int ni = 0; ni < 4; ni++) {
                int k0 = t * TN + warp_n * 32 + ni * 8 + (l & 3) * 2;
                float c0 = acc[mi][ni][0], c1 = acc[mi][ni][1];
                float c2 = acc[mi][ni][2], c3 = acc[mi][ni][3];
                int i0 = mi * 2, i1 = mi * 2 + 1;
                if (c0 > best[i0]) { best[i0] = c0; bidx[i0] = k0; }
                if (c1 > best[i0]) { best[i0] = c1; bidx[i0] = k0 + 1; }
                if (c2 > best[i1]) { best[i1] = c2; bidx[i1] = k0; }
                if (c3 > best[i1]) { best[i1] = c3; bidx[i1] = k0 + 1; }
            }
        }
        __syncthreads();
        if (tid == 0 && t + 2 < NTILE) {
            uint32_t mb = sb + SM_CTRL + ((t & 1) ? MB_B1 : MB_B0);
            MBAR_EXPECT_TX(mb, B_BYTES);
            bulk_g2s(bbuf, g_B + (size_t)(t + 2) * B_BYTES, B_BYTES, mb);
        }
    }

    float* red_s = (float*)(smem + SM_REDS);
    int*   red_i = (int*)(smem + SM_REDI);
    int*   bks   = (int*)(smem + SM_BKS);
    float* lsum  = (float*)(smem + SM_LSUM);
    const int e = warp_n * 4 + (l & 3);
    #pragma unroll
    for (int mi = 0; mi < 2; mi++) {
        #pragma unroll
        for (int h = 0; h < 2; h++) {
            int row = warp_m * 32 + mi * 16 + (l >> 2) + h * 8;
            red_s[row * 16 + e] = best[mi * 2 + h];
            red_i[row * 16 + e] = bidx[mi * 2 + h];
        }
    }
    __syncthreads();
    if (tid < TM) {
        float bs = -1e30f; int bk = 0;
        #pragma unroll
        for (int q = 0; q < 16; q++) {
            float s = red_s[tid * 16 + q];
            int   k = red_i[tid * 16 + q];
            if (s > bs || (s == bs && k < bk)) { bs = s; bk = k; }
        }
        bks[tid] = bk;
    }
    __syncthreads();
    // EXACT loss: 4 threads/row; features re-read from global (L2/HBM)
    {
        const int row = tid >> 2, q = tid & 3;
        const int bk  = bks[row];
        const float4* frow = (const float4*)(features + (size_t)(blockIdx.x * TM + row) * D);
        const float4* crow = (const float4*)(centers + (size_t)bk * D);
        float dot = 0.0f;
        #pragma unroll
        for (int j = 0; j < 8; j++) {
            int i4 = q * 8 + j;
            float4 a = frow[i4];
            float4 c = crow[i4];
            dot += a.x * c.x + a.y * c.y + a.z * c.z + a.w * c.w;
        }
        dot += __shfl_xor_sync(0xffffffffu, dot, 1);
        dot += __shfl_xor_sync(0xffffffffu, dot, 2);
        if (q == 0) {
            float rinv = ((float*)(smem + SM_RINV))[row];
            lsum[row] = 1.0f + g_cnormsq[bk] - 2.0f * rinv * dot;
        }
    }
    __syncthreads();
    #pragma unroll
    for (int s = TM / 2; s > 0; s >>= 1) {
        if (tid < s) lsum[tid] += lsum[tid + s];
        __syncthreads();
    }

    __shared__ unsigned int is_last;
    if (tid == 0) {
        g_partial[blockIdx.x] = lsum[0];
        __threadfence();
        is_last = (atomicAdd(&g_ctr, 1u) == NBLK - 1u);
    }
    __syncthreads();

    if (is_last) {
        __threadfence();
        double* sd = (double*)(smem + SM_SD);
        double s = 0.0;
        for (int i = tid; i < NBLK; i += 256)
            s += (double)(*(volatile float*)&g_partial[i]);
        sd[tid] = s;
        __syncthreads();
        for (int st = 128; st > 0; st >>= 1) {
            if (tid < st) sd[tid] += sd[tid + st];
            __syncthreads();
        }
        if (tid == 0) {
            out[0] = (float)(sd[0] / (double)N_FEAT);
            g_ctr = 0;
        }
    }
}

extern "C" void kernel_launch(void* const* d_in, const int* in_sizes, int n_in,
                              void* d_out, int out_size) {
    const float* features = (const float*)d_in[0];
    const float* centers  = (const float*)d_in[1];
    float* out = (float*)d_out;

    cudaFuncSetAttribute(gemm_argmax_mma,
                         cudaFuncAttributeMaxDynamicSharedMemorySize, SMEM_TOTAL);

    prep_centers<<<K, D>>>(centers);
    gemm_argmax_mma<<<NBLK, 256, SMEM_TOTAL>>>(features, centers, out);
}